// round 16
// baseline (speedup 1.0000x reference)
#include <cuda_runtime.h>

#define T     4096
#define TQ    1024         // float4s per array
#define NTH   544          // 17 warps, full-row CTA
#define W2    524          // pair-row width; W2 % 8 == 4 -> staging conflict-free
#define BUFP  (4 * W2)     // 2096 pairs per buffer (16768 B)
#define NSTG  1039         // float4s staged per array (buffer samples 0..4159)
#define SMEM_BYTES (4 * BUFP * 8)   // 67072 B

typedef unsigned long long u64;

// db4 synthesis filters pre-scaled by 0.5 (the per-level factor)
#define L0c ( 0.5f *  0.23037781330885523f)
#define L1c ( 0.5f *  0.7148465705525415f)
#define L2c ( 0.5f *  0.6308807679295904f)
#define L3c ( 0.5f * -0.02798376941698385f)
#define L4c ( 0.5f * -0.18703481171888114f)
#define L5c ( 0.5f *  0.030841381835986965f)
#define L6c ( 0.5f *  0.032883011666982945f)
#define L7c ( 0.5f * -0.010597401784997278f)
// rec_hi[k] = (-1)^k * rec_lo[7-k]
#define H0c ( L7c)
#define H1c (-L6c)
#define H2c ( L5c)
#define H3c (-L4c)
#define H4c ( L3c)
#define H5c (-L2c)
#define H6c ( L1c)
#define H7c (-L0c)

// Packed (x == y) coefficient pairs for FFMA2 (loaded as LDC.64)
__constant__ float2 CL2[8] = {
    {L0c,L0c},{L1c,L1c},{L2c,L2c},{L3c,L3c},{L4c,L4c},{L5c,L5c},{L6c,L6c},{L7c,L7c}};
__constant__ float2 CH2[8] = {
    {H0c,H0c},{H1c,H1c},{H2c,H2c},{H3c,H3c},{H4c,H4c},{H5c,H5c},{H6c,H6c},{H7c,H7c}};

__device__ __forceinline__ void fma2(u64& d, u64 c, u64 v) {
    asm("fma.rn.f32x2 %0, %1, %2, %0;" : "+l"(d) : "l"(c), "l"(v));
}

// 4-row pair-transposed layout: pair p at phys64 = (p & 3)*W2 + (p >> 2).
// Thread pair-base is 4t, so window accesses are LDS.64 [Rbase + imm],
// lanes consecutive -> conflict-free.

__device__ __forceinline__ void stage(u64* __restrict__ s,
                                      const float4* __restrict__ g4,
                                      int f4base, int tid) {
#pragma unroll
    for (int i = 0; i < 2; ++i) {
        int idx = tid + i * NTH;
        if (idx < NSTG) {
            float4 v = __ldg(&g4[(f4base + idx) & (TQ - 1)]);   // circular
            int r = 2 * (idx & 1);           // (2idx) & 3
            int q = idx >> 1;                // (2idx) >> 2
            *(float2*)(s + (r + 0) * W2 + q) = make_float2(v.x, v.y);
            *(float2*)(s + (r + 1) * W2 + q) = make_float2(v.z, v.w);
        }
    }
}

struct Pref2 { float4 v[2]; };

__device__ __forceinline__ void prefetch(Pref2& p, const float4* __restrict__ g4,
                                         int f4base, int tid) {
#pragma unroll
    for (int i = 0; i < 2; ++i) {
        int idx = tid + i * NTH;
        p.v[i] = (idx < NSTG) ? __ldg(&g4[(f4base + idx) & (TQ - 1)])
                              : make_float4(0.f, 0.f, 0.f, 0.f);
    }
}

__device__ __forceinline__ void commit(u64* __restrict__ s, const Pref2& p, int tid) {
#pragma unroll
    for (int i = 0; i < 2; ++i) {
        int idx = tid + i * NTH;
        if (idx < NSTG) {
            int r = 2 * (idx & 1);
            int q = idx >> 1;
            *(float2*)(s + (r + 0) * W2 + q) = make_float2(p.v[i].x, p.v[i].y);
            *(float2*)(s + (r + 1) * W2 + q) = make_float2(p.v[i].z, p.v[i].w);
        }
    }
}

// Even-dilation FFMA2 pass: acc pair kk (samples 2kk,2kk+1 of the octet at
// 8t+OFF) gets tap m from pair q = kk + (D*(3-m)+OFF)/2 (all shifts even).
template <int D, int OFF, int QMAX>
__device__ __forceinline__ void pass_even2(const u64* __restrict__ buf, u64* acc,
                                           const float2* __restrict__ coef, int t) {
    u64 c[8];
    const u64* cu = (const u64*)coef;        // LDC.64
#pragma unroll
    for (int m = 0; m < 8; ++m) c[m] = cu[m];
    const u64* p = buf + t;
#pragma unroll
    for (int q = 0; q <= QMAX; ++q) {
        u64 v = p[(q & 3) * W2 + (q >> 2)];
#pragma unroll
        for (int m = 0; m < 8; ++m) {
            const int kk = q - (D * (3 - m) + OFF) / 2;
            if (kk >= 0 && kk < 4) fma2(acc[kk], c[m], v);
        }
    }
}

// D=1 scalar pass (OFF=8): octet j = 2q(+1) - 8 - (3-m); FFMA-imm.
template <int D, int OFF, int QMIN, int QMAX>
__device__ __forceinline__ void pass_scalar(const u64* __restrict__ buf,
                                            float* acc, const float* cf, int t) {
    const u64* p = buf + t;
#pragma unroll
    for (int q = QMIN; q <= QMAX; ++q) {
        u64 vv = p[(q & 3) * W2 + (q >> 2)];
        float2 v = *(float2*)&vv;
#pragma unroll
        for (int m = 0; m < 8; ++m) {
            {   const int j = 2 * q     - OFF - D * (3 - m);
                if (j >= 0 && j < 8) acc[j] = fmaf(cf[m], v.x, acc[j]); }
            {   const int j = 2 * q + 1 - OFF - D * (3 - m);
                if (j >= 0 && j < 8) acc[j] = fmaf(cf[m], v.y, acc[j]); }
        }
    }
}

extern __shared__ u64 dsm[];

__global__ void __launch_bounds__(NTH, 3)
iswt_kernel(const float* __restrict__ x, float* __restrict__ out) {
    u64* bA = dsm + 0 * BUFP;   // cA3, then cD1
    u64* bB = dsm + 1 * BUFP;   // cD3, then R2
    u64* bC = dsm + 2 * BUFP;   // cD2
    u64* bD = dsm + 3 * BUFP;   // R1

    const int bn  = blockIdx.x;                // row in [0, 2048); full row per CTA
    const int tid = threadIdx.x;
    const float* g = x + (size_t)bn * 4 * T;   // cA3 | cD3 | cD2 | cD1
    const float4* g4 = (const float4*)g;

    // Buffer origins (global sample of buffer logical 0): -32 / -16 / -8.
    // Circular wrap handled by the & (TQ-1) in staging.
    stage(bA, g4 + 0 * TQ, -8, tid);           // cA3  (origin -32)
    stage(bB, g4 + 1 * TQ, -8, tid);           // cD3  (origin -32)
    stage(bC, g4 + 2 * TQ, -4, tid);           // cD2  (origin -16)
    Pref2 pE; prefetch(pE, g4 + 3 * TQ, -2, tid);   // cD1 (origin -8) -> regs
    __syncthreads();

    // Level 1 (d=4, OFF=16): cA3,cD3 -> R1 (origin -16), octets t<516, FFMA2
    // (t=515 reads input pairs up to 2077 = staged sample 4155 < 4160 staged)
    if (tid < 516) {
        u64 acc[4];
#pragma unroll
        for (int k = 0; k < 4; ++k) acc[k] = 0ULL;
        pass_even2<4, 16, 17>(bA, acc, CL2, tid);
        pass_even2<4, 16, 17>(bB, acc, CH2, tid);
        u64* p = bD + tid;
#pragma unroll
        for (int k = 0; k < 4; ++k) p[k * W2] = acc[k];
    }
    __syncthreads();

    // cA3 dead -> commit cD1 (origin -8) into bA; data long arrived.
    commit(bA, pE, tid);

    // Level 2 (d=2, OFF=8): R1,cD2 -> R2 (origin -8) into bB, octets t<514
    // (R2 must cover global up to 4099 for L3's t=511 tail taps)
    if (tid < 514) {
        u64 acc[4];
#pragma unroll
        for (int k = 0; k < 4; ++k) acc[k] = 0ULL;
        pass_even2<2, 8, 10>(bD, acc, CL2, tid);
        pass_even2<2, 8, 10>(bC, acc, CH2, tid);
        u64* p = bB + tid;
#pragma unroll
        for (int k = 0; k < 4; ++k) p[k * W2] = acc[k];
    }
    __syncthreads();

    // Level 3 (d=1, OFF=8): R2,cD1 -> global [8t, 8t+8), octets t<512, scalar
    if (tid < 512) {
        const float CFL[8] = {L0c,L1c,L2c,L3c,L4c,L5c,L6c,L7c};
        const float CFH[8] = {H0c,H1c,H2c,H3c,H4c,H5c,H6c,H7c};
        float acc[8];
#pragma unroll
        for (int j = 0; j < 8; ++j) acc[j] = 0.0f;
        pass_scalar<1, 8, 2, 9>(bB, acc, CFL, tid);
        pass_scalar<1, 8, 2, 9>(bA, acc, CFH, tid);
        float4* o = (float4*)(out + (size_t)bn * T + tid * 8);
        o[0] = make_float4(acc[0], acc[1], acc[2], acc[3]);
        o[1] = make_float4(acc[4], acc[5], acc[6], acc[7]);
    }
}

extern "C" void kernel_launch(void* const* d_in, const int* in_sizes, int n_in,
                              void* d_out, int out_size) {
    const float* x = (const float*)d_in[0];
    float* out = (float*)d_out;
    cudaFuncSetAttribute(iswt_kernel,
                         cudaFuncAttributeMaxDynamicSharedMemorySize, SMEM_BYTES);
    iswt_kernel<<<2048, NTH, SMEM_BYTES>>>(x, out);
}

// round 17
// speedup vs baseline: 1.1490x; 1.1490x over previous
#include <cuda_runtime.h>

#define T     4096
#define TQ    1024         // float4s per array
#define NTH   288          // 9 warps
#define W2    268          // pair-row width; W2 % 8 == 4 -> staging conflict-free
#define BUFP  (4 * W2)     // 1072 pairs per buffer (8576 B)
#define NSTG  527          // float4s staged per array (pairs 0..1053)

typedef unsigned long long u64;

// db4 synthesis filters pre-scaled by 0.5 (the per-level factor)
#define L0c ( 0.5f *  0.23037781330885523f)
#define L1c ( 0.5f *  0.7148465705525415f)
#define L2c ( 0.5f *  0.6308807679295904f)
#define L3c ( 0.5f * -0.02798376941698385f)
#define L4c ( 0.5f * -0.18703481171888114f)
#define L5c ( 0.5f *  0.030841381835986965f)
#define L6c ( 0.5f *  0.032883011666982945f)
#define L7c ( 0.5f * -0.010597401784997278f)
// rec_hi[k] = (-1)^k * rec_lo[7-k]
#define H0c ( L7c)
#define H1c (-L6c)
#define H2c ( L5c)
#define H3c (-L4c)
#define H4c ( L3c)
#define H5c (-L2c)
#define H6c ( L1c)
#define H7c (-L0c)

// Packed (x == y) coefficient pairs for FFMA2 (loaded as LDC.64)
__constant__ float2 CL2[8] = {
    {L0c,L0c},{L1c,L1c},{L2c,L2c},{L3c,L3c},{L4c,L4c},{L5c,L5c},{L6c,L6c},{L7c,L7c}};
__constant__ float2 CH2[8] = {
    {H0c,H0c},{H1c,H1c},{H2c,H2c},{H3c,H3c},{H4c,H4c},{H5c,H5c},{H6c,H6c},{H7c,H7c}};

__device__ __forceinline__ void fma2(u64& d, u64 c, u64 v) {
    asm("fma.rn.f32x2 %0, %1, %2, %0;" : "+l"(d) : "l"(c), "l"(v));
}

// 4-row pair-transposed layout: pair p at phys64 = (p & 3)*W2 + (p >> 2).
// Thread pair-base is 4t, so window accesses are LDS.64 [Rbase + imm],
// lanes consecutive -> conflict-free.

__device__ __forceinline__ void stage(u64* __restrict__ s,
                                      const float4* __restrict__ g4,
                                      int f4base, int tid) {
#pragma unroll
    for (int i = 0; i < 2; ++i) {
        int idx = tid + i * NTH;
        if (idx < NSTG) {
            float4 v = __ldg(&g4[(f4base + idx) & (TQ - 1)]);
            int r = 2 * (idx & 1);           // (2idx) & 3
            int q = idx >> 1;                // (2idx) >> 2
            *(float2*)(s + (r + 0) * W2 + q) = make_float2(v.x, v.y);
            *(float2*)(s + (r + 1) * W2 + q) = make_float2(v.z, v.w);
        }
    }
}

struct Pref2 { float4 v[2]; };

__device__ __forceinline__ void prefetch(Pref2& p, const float4* __restrict__ g4,
                                         int f4base, int tid) {
#pragma unroll
    for (int i = 0; i < 2; ++i) {
        int idx = tid + i * NTH;
        p.v[i] = (idx < NSTG) ? __ldg(&g4[(f4base + idx) & (TQ - 1)])
                              : make_float4(0.f, 0.f, 0.f, 0.f);
    }
}

__device__ __forceinline__ void commit(u64* __restrict__ s, const Pref2& p, int tid) {
#pragma unroll
    for (int i = 0; i < 2; ++i) {
        int idx = tid + i * NTH;
        if (idx < NSTG) {
            int r = 2 * (idx & 1);
            int q = idx >> 1;
            *(float2*)(s + (r + 0) * W2 + q) = make_float2(p.v[i].x, p.v[i].y);
            *(float2*)(s + (r + 1) * W2 + q) = make_float2(p.v[i].z, p.v[i].w);
        }
    }
}

// Even-dilation FFMA2 pass: acc pair kk (samples 2kk,2kk+1 of the octet at
// 8t+OFF) gets tap m from pair q = kk + (D*(3-m)+OFF)/2 (all shifts even).
template <int D, int OFF, int QMAX>
__device__ __forceinline__ void pass_even2(const u64* __restrict__ buf, u64* acc,
                                           const float2* __restrict__ coef, int t) {
    u64 c[8];
    const u64* cu = (const u64*)coef;        // LDC.64
#pragma unroll
    for (int m = 0; m < 8; ++m) c[m] = cu[m];
    const u64* p = buf + t;
#pragma unroll
    for (int q = 0; q <= QMAX; ++q) {
        u64 v = p[(q & 3) * W2 + (q >> 2)];
#pragma unroll
        for (int m = 0; m < 8; ++m) {
            const int kk = q - (D * (3 - m) + OFF) / 2;
            if (kk >= 0 && kk < 4) fma2(acc[kk], c[m], v);
        }
    }
}

// D=1 hybrid pass (OFF=8): acc[j] += coef[m] * buf[8t + j + 11 - m].
// Even shifts r = 11-m (m odd): aligned pair taps -> FFMA2 into accE,
//   accE[k] += c2[m] * pair(q), k = q - (11-m)/2.
// Odd shifts (m even): scalar FFMA-imm into accO (as before).
__device__ __forceinline__ void pass_d1_hyb(const u64* __restrict__ buf,
                                            u64* accE, float* accO,
                                            const float2* __restrict__ coef,
                                            const float* cf, int t) {
    u64 c2[4];
    const u64* cu = (const u64*)coef;        // LDC.64: m = 1,3,5,7
#pragma unroll
    for (int i = 0; i < 4; ++i) c2[i] = cu[2 * i + 1];
    const u64* p = buf + t;
#pragma unroll
    for (int q = 2; q <= 9; ++q) {
        u64 vv = p[(q & 3) * W2 + (q >> 2)];
        // paired even-shift taps (m = 1,3,5,7 -> k = q-5, q-4, q-3, q-2)
#pragma unroll
        for (int i = 0; i < 4; ++i) {
            const int m = 2 * i + 1;
            const int k = q - (11 - m) / 2;
            if (k >= 0 && k < 4) fma2(accE[k], c2[i], vv);
        }
        // scalar odd-shift taps (m = 0,2,4,6)
        float2 v = *(float2*)&vv;
#pragma unroll
        for (int m = 0; m < 8; m += 2) {
            {   const int j = 2 * q - 11 + m;          // from v.x (sample 2q)
                if (j >= 0 && j < 8) accO[j] = fmaf(cf[m], v.x, accO[j]); }
            {   const int j = 2 * q - 10 + m;          // from v.y (sample 2q+1)
                if (j >= 0 && j < 8) accO[j] = fmaf(cf[m], v.y, accO[j]); }
        }
    }
}

__global__ void __launch_bounds__(NTH, 5)
iswt_kernel(const float* __restrict__ x, float* __restrict__ out) {
    __shared__ u64 bA[BUFP];   // cA3, then cD1
    __shared__ u64 bB[BUFP];   // cD3, then R2
    __shared__ u64 bC[BUFP];   // cD2
    __shared__ u64 bD[BUFP];   // R1

    const int bn  = blockIdx.x >> 1;           // row in [0, 2048)
    const int S   = (blockIdx.x & 1) << 11;    // chunk start: 0 or 2048
    const int tid = threadIdx.x;
    const float* g = x + (size_t)bn * 4 * T;   // cA3 | cD3 | cD2 | cD1
    const float4* g4 = (const float4*)g;

    const int o32 = (S - 32) >> 2;             // buffer origins (float4 index)
    const int o16 = (S - 16) >> 2;
    const int o8  = (S - 8)  >> 2;

    stage(bA, g4 + 0 * TQ, o32, tid);          // cA3  (origin S-32)
    stage(bB, g4 + 1 * TQ, o32, tid);          // cD3  (origin S-32)
    stage(bC, g4 + 2 * TQ, o16, tid);          // cD2  (origin S-16)
    Pref2 pE; prefetch(pE, g4 + 3 * TQ, o8, tid);   // cD1 -> regs (in flight)
    __syncthreads();

    // Level 1 (d=4, OFF=16): cA3,cD3 -> R1 (origin S-16), 260 threads, FFMA2
    if (tid < 260) {
        u64 acc[4];
#pragma unroll
        for (int k = 0; k < 4; ++k) acc[k] = 0ULL;
        pass_even2<4, 16, 17>(bA, acc, CL2, tid);
        pass_even2<4, 16, 17>(bB, acc, CH2, tid);
        u64* p = bD + tid;
#pragma unroll
        for (int k = 0; k < 4; ++k) p[k * W2] = acc[k];
    }
    __syncthreads();

    // cA3 dead -> commit cD1 (origin S-8) into bA; data long arrived.
    commit(bA, pE, tid);

    // Level 2 (d=2, OFF=8): R1,cD2 -> R2 (origin S-8) into bB, 258 threads, FFMA2
    if (tid < 258) {
        u64 acc[4];
#pragma unroll
        for (int k = 0; k < 4; ++k) acc[k] = 0ULL;
        pass_even2<2, 8, 10>(bD, acc, CL2, tid);
        pass_even2<2, 8, 10>(bC, acc, CH2, tid);
        u64* p = bB + tid;
#pragma unroll
        for (int k = 0; k < 4; ++k) p[k * W2] = acc[k];
    }
    __syncthreads();

    // Level 3 (d=1, OFF=8): R2,cD1 -> global [S+8t, S+8t+8), 256 threads, hybrid
    if (tid < 256) {
        const float CFL[8] = {L0c,L1c,L2c,L3c,L4c,L5c,L6c,L7c};
        const float CFH[8] = {H0c,H1c,H2c,H3c,H4c,H5c,H6c,H7c};
        u64   accE[4];
        float accO[8];
#pragma unroll
        for (int k = 0; k < 4; ++k) accE[k] = 0ULL;
#pragma unroll
        for (int j = 0; j < 8; ++j) accO[j] = 0.0f;
        pass_d1_hyb(bB, accE, accO, CL2, CFL, tid);
        pass_d1_hyb(bA, accE, accO, CH2, CFH, tid);
        // merge: x[2k] = accO[2k] + lo(accE[k]); x[2k+1] = accO[2k+1] + hi(accE[k])
        float r[8];
#pragma unroll
        for (int k = 0; k < 4; ++k) {
            float2 e = *(float2*)&accE[k];
            r[2 * k + 0] = accO[2 * k + 0] + e.x;
            r[2 * k + 1] = accO[2 * k + 1] + e.y;
        }
        float4* o = (float4*)(out + (size_t)bn * T + S + tid * 8);
        o[0] = make_float4(r[0], r[1], r[2], r[3]);
        o[1] = make_float4(r[4], r[5], r[6], r[7]);
    }
}

extern "C" void kernel_launch(void* const* d_in, const int* in_sizes, int n_in,
                              void* d_out, int out_size) {
    const float* x = (const float*)d_in[0];
    float* out = (float*)d_out;
    iswt_kernel<<<4096, NTH>>>(x, out);
}